// round 9
// baseline (speedup 1.0000x reference)
#include <cuda_runtime.h>
#include <cuda_bf16.h>

#define OUT_DIM 64
#define IN_DIM 128
#define MAX_POOL 16384
#define MAX_EDGES 65536
#define CAP 32                 // bucket capacity per pool entry

__device__ int g_counts[MAX_POOL + 1];        // bucket alloc cursors + spill counter
__device__ int g_bucket[MAX_POOL * CAP];      // memset to -1 each call
__device__ int g_spill[MAX_EDGES];

// ---------------------------------------------------------------------------
// Single-pass counting scatter into fixed-capacity buckets; overflow -> spill.
__global__ void bucket_kernel(const int* __restrict__ idx, int E, int npool) {
    int i = blockIdx.x * blockDim.x + threadIdx.x;
    if (i < E) {
        int id = idx[i];
        int p = atomicAdd(&g_counts[id], 1);
        if (p < CAP) {
            g_bucket[id * CAP + p] = i;
        } else {
            int s = atomicAdd(&g_counts[npool], 1);
            if (s < MAX_EDGES) g_spill[s] = i;
        }
    }
}

// ---------------------------------------------------------------------------
// Hot path: grid (npool, 2). CTA (w, half) owns output rows [half*32, half*32+32)
// of pool entry w: 16KB of W, 4 rows per warp (wv[4] = 16 regs). Low register
// footprint (launch_bounds min 5 CTAs/SM) maximizes resident CTAs -> more
// independent W streams in flight per SM -> higher DRAM utilization.
__global__ __launch_bounds__(256, 5) void compute_kernel(
    const float* __restrict__ x,      // [E, 128]
    const float* __restrict__ Wpool,  // [P, 64, 128]
    const float* __restrict__ bpool,  // [P, 64]
    float* __restrict__ out)          // [E, 64]
{
    int w    = blockIdx.x;
    int half = blockIdx.y;
    int warp = threadIdx.x >> 5;
    int lane = threadIdx.x & 31;

    // Issue all independent loads up front: edge-id slice + W slice.
    int se = g_bucket[w * CAP + lane];                  // -1 if slot empty

    int rowbase = half * 32 + warp * 4;                 // first of this warp's 4 rows
    const float4* Wg = reinterpret_cast<const float4*>(Wpool)
                       + (size_t)w * 2048 + (size_t)rowbase * 32;
    float4 wv[4];
    #pragma unroll
    for (int j = 0; j < 4; j++)
        wv[j] = Wg[j * 32 + lane];   // wv[j] = W[rowbase+j][4l..4l+4)

    int c = __popc(__ballot_sync(~0u, se >= 0));        // group size (0..32)
    if (c == 0) return;

    // lane 0..3 will own row rloc (bit-reversed 2-bit lane id)
    int rloc = 2 * (lane & 1) + ((lane >> 1) & 1);
    int orow = rowbase + rloc;
    float bias = bpool[(size_t)w * OUT_DIM + orow];

    const float4* X = reinterpret_cast<const float4*>(x);
    float4 z = make_float4(0.f, 0.f, 0.f, 0.f);

    int eA = __shfl_sync(~0u, se, 0);
    float4 xA = X[(size_t)eA * 32 + lane];

    for (int t = 0; t < c; t++) {
        // depth-1 prefetch of next edge's x
        int eB = __shfl_sync(~0u, se, (t + 1) & 31);
        float4 xB = z;
        if (t + 1 < c) xB = X[(size_t)eB * 32 + lane];

        // 4 row partials over this lane's 4 k's (16 FMA)
        float v0 = wv[0].x * xA.x, v1 = wv[1].x * xA.x;
        float v2 = wv[2].x * xA.x, v3 = wv[3].x * xA.x;
        v0 = fmaf(wv[0].y, xA.y, v0); v1 = fmaf(wv[1].y, xA.y, v1);
        v2 = fmaf(wv[2].y, xA.y, v2); v3 = fmaf(wv[3].y, xA.y, v3);
        v0 = fmaf(wv[0].z, xA.z, v0); v1 = fmaf(wv[1].z, xA.z, v1);
        v2 = fmaf(wv[2].z, xA.z, v2); v3 = fmaf(wv[3].z, xA.z, v3);
        v0 = fmaf(wv[0].w, xA.w, v0); v1 = fmaf(wv[1].w, xA.w, v1);
        v2 = fmaf(wv[2].w, xA.w, v2); v3 = fmaf(wv[3].w, xA.w, v3);

        // fold 4 rows x 32 lanes -> lanes 0..3 hold final row values
        bool b0 = lane & 1;
        float p0 = __shfl_xor_sync(~0u, v0, 1), p1 = __shfl_xor_sync(~0u, v1, 1);
        float p2 = __shfl_xor_sync(~0u, v2, 1), p3 = __shfl_xor_sync(~0u, v3, 1);
        float a0 = b0 ? (v2 + p2) : (v0 + p0);
        float a1 = b0 ? (v3 + p3) : (v1 + p1);
        bool b1 = lane & 2;
        float q0 = __shfl_xor_sync(~0u, a0, 2), q1 = __shfl_xor_sync(~0u, a1, 2);
        float acc = b1 ? (a1 + q1) : (a0 + q0);
        acc += __shfl_xor_sync(~0u, acc, 4);
        acc += __shfl_xor_sync(~0u, acc, 8);
        acc += __shfl_xor_sync(~0u, acc, 16);

        if (lane < 4) {
            float y = acc + bias;
            out[(size_t)eA * OUT_DIM + orow] = y > 0.f ? y : 0.f;
        }

        eA = eB; xA = xB;
    }
}

// ---------------------------------------------------------------------------
// Spill slow path: normally zero work, early exit.
__global__ __launch_bounds__(256) void spill_kernel(
    const float* __restrict__ x,
    const float* __restrict__ Wpool,
    const float* __restrict__ bpool,
    const int*   __restrict__ idx,
    float* __restrict__ out,
    int npool)
{
    int nspill = g_counts[npool];
    if (nspill == 0) return;
    if (nspill > MAX_EDGES) nspill = MAX_EDGES;

    int warp = threadIdx.x >> 5;
    int lane = threadIdx.x & 31;
    const float4* X = reinterpret_cast<const float4*>(x);

    for (int s = blockIdx.x * 8 + warp; s < nspill; s += gridDim.x * 8) {
        int e = g_spill[s];
        int p = idx[e];
        const float4* Wr = reinterpret_cast<const float4*>(Wpool) + (size_t)p * 2048;
        #pragma unroll
        for (int rr = 0; rr < 2; rr++) {
            int row = lane * 2 + rr;
            float acc = 0.f;
            for (int kk = 0; kk < 32; kk++) {
                float4 a = Wr[row * 32 + kk];
                float4 b = X[(size_t)e * 32 + kk];
                acc = fmaf(a.x, b.x, acc);
                acc = fmaf(a.y, b.y, acc);
                acc = fmaf(a.z, b.z, acc);
                acc = fmaf(a.w, b.w, acc);
            }
            acc += bpool[(size_t)p * OUT_DIM + row];
            out[(size_t)e * OUT_DIM + row] = acc > 0.f ? acc : 0.f;
        }
    }
}

// ---------------------------------------------------------------------------
extern "C" void kernel_launch(void* const* d_in, const int* in_sizes, int n_in,
                              void* d_out, int out_size) {
    const float* x     = (const float*)d_in[0];  // [E,128,1]
    const int*   idx   = (const int*)d_in[1];    // [E]
    const float* Wpool = (const float*)d_in[2];  // [P,64,128]
    const float* bpool = (const float*)d_in[3];  // [P,64,1]
    float* out = (float*)d_out;                  // [E,64,1]

    int E     = in_sizes[1];
    int npool = in_sizes[3] / OUT_DIM;
    if (npool > MAX_POOL) npool = MAX_POOL;      // defensive

    void* counts_ptr = nullptr;
    void* bucket_ptr = nullptr;
    cudaGetSymbolAddress(&counts_ptr, g_counts);
    cudaGetSymbolAddress(&bucket_ptr, g_bucket);
    cudaMemsetAsync(counts_ptr, 0, (size_t)(npool + 1) * sizeof(int));
    cudaMemsetAsync(bucket_ptr, 0xFF, (size_t)npool * CAP * sizeof(int));

    int eb = (E + 255) / 256;
    bucket_kernel<<<eb, 256>>>(idx, E, npool);
    dim3 cgrid(npool, 2);
    compute_kernel<<<cgrid, 256>>>(x, Wpool, bpool, out);
    spill_kernel<<<64, 256>>>(x, Wpool, bpool, idx, out, npool);
}

// round 10
// speedup vs baseline: 1.2182x; 1.2182x over previous
#include <cuda_runtime.h>
#include <cuda_bf16.h>

#define OUT_DIM 64
#define IN_DIM 128
#define MAX_POOL 16384
#define MAX_EDGES 65536
#define CAP 32                 // bucket capacity per pool entry

__device__ int g_counts[MAX_POOL + 1];        // bucket alloc cursors + spill counter
__device__ int g_bucket[MAX_POOL * CAP];      // memset to -1 each call
__device__ int g_spill[MAX_EDGES];

// ---------------------------------------------------------------------------
// Single-pass counting scatter into fixed-capacity buckets; overflow -> spill.
__global__ void bucket_kernel(const int* __restrict__ idx, int E, int npool) {
    int i = blockIdx.x * blockDim.x + threadIdx.x;
    if (i < E) {
        int id = idx[i];
        int p = atomicAdd(&g_counts[id], 1);
        if (p < CAP) {
            g_bucket[id * CAP + p] = i;
        } else {
            int s = atomicAdd(&g_counts[npool], 1);
            if (s < MAX_EDGES) g_spill[s] = i;
        }
    }
}

// ---------------------------------------------------------------------------
__device__ __forceinline__ void partials8(float v[8], const float4 wv[8],
                                          const float4& xv) {
    #pragma unroll
    for (int i = 0; i < 8; i++) v[i] = wv[i].x * xv.x;
    #pragma unroll
    for (int i = 0; i < 8; i++) v[i] = fmaf(wv[i].y, xv.y, v[i]);
    #pragma unroll
    for (int i = 0; i < 8; i++) v[i] = fmaf(wv[i].z, xv.z, v[i]);
    #pragma unroll
    for (int i = 0; i < 8; i++) v[i] = fmaf(wv[i].w, xv.w, v[i]);
}

// 5-stage butterfly: 8 row-partials x 32 lanes -> final row value in lanes 0..7
__device__ __forceinline__ float fold8(const float v[8], int lane) {
    bool b0 = lane & 1;
    float a0, a1, a2, a3;
    {
        float p0 = __shfl_xor_sync(~0u, v[0], 1), p1 = __shfl_xor_sync(~0u, v[1], 1);
        float p2 = __shfl_xor_sync(~0u, v[2], 1), p3 = __shfl_xor_sync(~0u, v[3], 1);
        float p4 = __shfl_xor_sync(~0u, v[4], 1), p5 = __shfl_xor_sync(~0u, v[5], 1);
        float p6 = __shfl_xor_sync(~0u, v[6], 1), p7 = __shfl_xor_sync(~0u, v[7], 1);
        a0 = b0 ? (v[4] + p4) : (v[0] + p0);
        a1 = b0 ? (v[5] + p5) : (v[1] + p1);
        a2 = b0 ? (v[6] + p6) : (v[2] + p2);
        a3 = b0 ? (v[7] + p7) : (v[3] + p3);
    }
    bool b1 = lane & 2;
    float c0, c1;
    {
        float q0 = __shfl_xor_sync(~0u, a0, 2), q1 = __shfl_xor_sync(~0u, a1, 2);
        float q2 = __shfl_xor_sync(~0u, a2, 2), q3 = __shfl_xor_sync(~0u, a3, 2);
        c0 = b1 ? (a2 + q2) : (a0 + q0);
        c1 = b1 ? (a3 + q3) : (a1 + q1);
    }
    bool b2 = lane & 4;
    float s0 = __shfl_xor_sync(~0u, c0, 4), s1 = __shfl_xor_sync(~0u, c1, 4);
    float acc = b2 ? (c1 + s1) : (c0 + s0);
    acc += __shfl_xor_sync(~0u, acc, 8);
    acc += __shfl_xor_sync(~0u, acc, 16);
    return acc;
}

// ---------------------------------------------------------------------------
// Persistent compute: grid = 4*SMs CTAs, each loops w += gridDim.x over pool
// entries. Kills the ~17 wave transitions of the 10000-CTA launch and hides
// the next group's bucket-id load under the current group's compute.
__global__ __launch_bounds__(256, 4) void compute_kernel(
    const float* __restrict__ x,      // [E, 128]
    const float* __restrict__ Wpool,  // [P, 64, 128]
    const float* __restrict__ bpool,  // [P, 64]
    float* __restrict__ out,          // [E, 64]
    int npool)
{
    int warp = threadIdx.x >> 5;
    int lane = threadIdx.x & 31;

    int rloc = 4 * (lane & 1) + 2 * ((lane >> 1) & 1) + ((lane >> 2) & 1);
    int orow = 8 * warp + rloc;

    const float4* X = reinterpret_cast<const float4*>(x);
    float4 z = make_float4(0.f, 0.f, 0.f, 0.f);

    int w = blockIdx.x;
    int se_next = (w < npool) ? g_bucket[w * CAP + lane] : -1;

    while (w < npool) {
        int se = se_next;

        // W slice for this group: 8 x coalesced LDG.128 (512B each).
        const float4* Wg = reinterpret_cast<const float4*>(Wpool)
                           + (size_t)w * 2048 + warp * 256;
        float4 wv[8];
        #pragma unroll
        for (int i = 0; i < 8; i++)
            wv[i] = Wg[i * 32 + lane];   // wv[i] = W[8*warp+i][4l..4l+4)

        // Prefetch NEXT group's edge-id slice now (hides its latency fully).
        int wn = w + gridDim.x;
        se_next = (wn < npool) ? g_bucket[wn * CAP + lane] : -1;

        int c = __popc(__ballot_sync(~0u, se >= 0));     // group size 0..32
        if (c > 0) {
            float bias = bpool[(size_t)w * OUT_DIM + orow];

            // prime pair pipeline: edges 0,1
            int eA = __shfl_sync(~0u, se, 0);
            int eB = __shfl_sync(~0u, se, 1);
            float4 xA = X[(size_t)eA * 32 + lane];
            float4 xB = (c > 1) ? X[(size_t)eB * 32 + lane] : z;

            int t = 0;
            while (t + 2 <= c) {
                int eC = __shfl_sync(~0u, se, (t + 2) & 31);
                int eD = __shfl_sync(~0u, se, (t + 3) & 31);
                float4 xC = z, xD = z;
                if (t + 2 < c) xC = X[(size_t)eC * 32 + lane];
                if (t + 3 < c) xD = X[(size_t)eD * 32 + lane];

                float vA[8], vB[8];
                partials8(vA, wv, xA);
                partials8(vB, wv, xB);
                float accA = fold8(vA, lane);
                float accB = fold8(vB, lane);

                if (lane < 8) {
                    float yA = accA + bias;
                    float yB = accB + bias;
                    out[(size_t)eA * OUT_DIM + orow] = yA > 0.f ? yA : 0.f;
                    out[(size_t)eB * OUT_DIM + orow] = yB > 0.f ? yB : 0.f;
                }

                eA = eC; xA = xC;
                eB = eD; xB = xD;
                t += 2;
            }
            if (t < c) {                         // odd tail
                float vA[8];
                partials8(vA, wv, xA);
                float accA = fold8(vA, lane);
                if (lane < 8) {
                    float yA = accA + bias;
                    out[(size_t)eA * OUT_DIM + orow] = yA > 0.f ? yA : 0.f;
                }
            }
        }
        w = wn;
    }
}

// ---------------------------------------------------------------------------
// Spill slow path: normally zero work, early exit.
__global__ __launch_bounds__(256) void spill_kernel(
    const float* __restrict__ x,
    const float* __restrict__ Wpool,
    const float* __restrict__ bpool,
    const int*   __restrict__ idx,
    float* __restrict__ out,
    int npool)
{
    int nspill = g_counts[npool];
    if (nspill == 0) return;
    if (nspill > MAX_EDGES) nspill = MAX_EDGES;

    int warp = threadIdx.x >> 5;
    int lane = threadIdx.x & 31;
    const float4* X = reinterpret_cast<const float4*>(x);

    for (int s = blockIdx.x * 8 + warp; s < nspill; s += gridDim.x * 8) {
        int e = g_spill[s];
        int p = idx[e];
        const float4* Wr = reinterpret_cast<const float4*>(Wpool) + (size_t)p * 2048;
        #pragma unroll
        for (int rr = 0; rr < 2; rr++) {
            int row = lane * 2 + rr;
            float acc = 0.f;
            for (int kk = 0; kk < 32; kk++) {
                float4 a = Wr[row * 32 + kk];
                float4 b = X[(size_t)e * 32 + kk];
                acc = fmaf(a.x, b.x, acc);
                acc = fmaf(a.y, b.y, acc);
                acc = fmaf(a.z, b.z, acc);
                acc = fmaf(a.w, b.w, acc);
            }
            acc += bpool[(size_t)p * OUT_DIM + row];
            out[(size_t)e * OUT_DIM + row] = acc > 0.f ? acc : 0.f;
        }
    }
}

// ---------------------------------------------------------------------------
extern "C" void kernel_launch(void* const* d_in, const int* in_sizes, int n_in,
                              void* d_out, int out_size) {
    const float* x     = (const float*)d_in[0];  // [E,128,1]
    const int*   idx   = (const int*)d_in[1];    // [E]
    const float* Wpool = (const float*)d_in[2];  // [P,64,128]
    const float* bpool = (const float*)d_in[3];  // [P,64,1]
    float* out = (float*)d_out;                  // [E,64,1]

    int E     = in_sizes[1];
    int npool = in_sizes[3] / OUT_DIM;
    if (npool > MAX_POOL) npool = MAX_POOL;      // defensive

    void* counts_ptr = nullptr;
    void* bucket_ptr = nullptr;
    cudaGetSymbolAddress(&counts_ptr, g_counts);
    cudaGetSymbolAddress(&bucket_ptr, g_bucket);
    cudaMemsetAsync(counts_ptr, 0, (size_t)(npool + 1) * sizeof(int));
    cudaMemsetAsync(bucket_ptr, 0xFF, (size_t)npool * CAP * sizeof(int));

    int sms = 148;
    cudaDeviceGetAttribute(&sms, cudaDevAttrMultiProcessorCount, 0);

    int eb = (E + 255) / 256;
    bucket_kernel<<<eb, 256>>>(idx, E, npool);

    int cgrid = 4 * sms;
    if (cgrid > npool) cgrid = npool;
    compute_kernel<<<cgrid, 256>>>(x, Wpool, bpool, out, npool);
    spill_kernel<<<64, 256>>>(x, Wpool, bpool, idx, out, npool);
}